// round 2
// baseline (speedup 1.0000x reference)
#include <cuda_runtime.h>
#include <cstdint>

#define B_   8
#define T_   2048
#define DIM_ 128
#define TU_  128
#define CHUNK_ 64

// out[b,u,d] = max(0, max_{t in segment u} x[b,t,d]); empty segment -> 0.
// tw sorted per batch => contiguous segments => register running-max + boundary flush.
// Values flushed are >= 0, so atomicMax on the uint bit pattern is exact for f32.
__global__ void __launch_bounds__(DIM_) twp_kernel(
    const float* __restrict__ x,
    const float* __restrict__ tw,
    const float* __restrict__ mask,     // bool materialized as float32
    const float* __restrict__ tw_uniq,
    float* __restrict__ out)
{
    const int b  = blockIdx.y;
    const int t0 = blockIdx.x * CHUNK_;

    __shared__ int seg_s[CHUNK_];

    const float twmin = tw_uniq[(size_t)b * TU_];   // broadcast load

    if (threadIdx.x < CHUNK_) {
        const int t = t0 + threadIdx.x;
        int s;
        if (mask[(size_t)b * T_ + t] != 0.0f) {
            s = (int)(tw[(size_t)b * T_ + t] - twmin);
            s = min(max(s, 0), TU_);
        } else {
            s = TU_;                       // sentinel: never flushed
        }
        seg_s[threadIdx.x] = s;
    }
    __syncthreads();

    const int d = threadIdx.x;            // 0..127
    const float* xp = x + ((size_t)b * T_ + t0) * DIM_ + d;
    unsigned int* outp = reinterpret_cast<unsigned int*>(out)
                         + (size_t)b * TU_ * DIM_ + d;

    float run = 0.0f;
    int cur = seg_s[0];

    #pragma unroll 8
    for (int i = 0; i < CHUNK_; ++i) {
        const int s = seg_s[i];
        if (s != cur) {
            if (cur < TU_ && run > 0.0f)
                atomicMax(outp + (size_t)cur * DIM_, __float_as_uint(run));
            run = 0.0f;
            cur = s;
        }
        run = fmaxf(run, fmaxf(xp[(size_t)i * DIM_], 0.0f));
    }
    if (cur < TU_ && run > 0.0f)
        atomicMax(outp + (size_t)cur * DIM_, __float_as_uint(run));
}

extern "C" void kernel_launch(void* const* d_in, const int* in_sizes, int n_in,
                              void* d_out, int out_size)
{
    const float* x       = (const float*)d_in[0];
    const float* tw      = (const float*)d_in[1];
    const float* mask    = (const float*)d_in[2];
    const float* tw_uniq = (const float*)d_in[3];
    float*       out     = (float*)d_out;

    // Output is poisoned; identity of relu-max is 0.0f (all-zero bytes).
    cudaMemsetAsync(d_out, 0, (size_t)out_size * sizeof(float));

    dim3 grid(T_ / CHUNK_, B_);   // 32 x 8 = 256 blocks
    twp_kernel<<<grid, DIM_>>>(x, tw, mask, tw_uniq, out);
}

// round 3
// speedup vs baseline: 1.1573x; 1.1573x over previous
#include <cuda_runtime.h>
#include <cstdint>

#define B_    8
#define T_    2048
#define DIM_  128
#define TU_   128

#define TOK_PER_BLOCK 32
#define ROWS          8
#define TOK_PER_ROW   4          // TOK_PER_BLOCK / ROWS
#define LANES         32         // DIM_/4 float4 lanes
#define THREADS       (ROWS * LANES)

// out[b,u,d] = max(0, max_{t: seg(t)==u} x[b,t,d]); empty segment -> 0.
// relu commutes with max => accumulate relu'd values with identity 0, and
// non-negative f32 order == uint order => uint atomicMax is exact.
// tw sorted per batch => each 4-token run touches ~1.25 segments.

__device__ __forceinline__ void flush4(unsigned int* p, float4 r)
{
    if (r.x > 0.0f) atomicMax(p + 0, __float_as_uint(r.x));
    if (r.y > 0.0f) atomicMax(p + 1, __float_as_uint(r.y));
    if (r.z > 0.0f) atomicMax(p + 2, __float_as_uint(r.z));
    if (r.w > 0.0f) atomicMax(p + 3, __float_as_uint(r.w));
}

__device__ __forceinline__ float4 relu4(float4 v)
{
    v.x = fmaxf(v.x, 0.0f); v.y = fmaxf(v.y, 0.0f);
    v.z = fmaxf(v.z, 0.0f); v.w = fmaxf(v.w, 0.0f);
    return v;
}

__device__ __forceinline__ float4 max4(float4 a, float4 b)
{
    a.x = fmaxf(a.x, b.x); a.y = fmaxf(a.y, b.y);
    a.z = fmaxf(a.z, b.z); a.w = fmaxf(a.w, b.w);
    return a;
}

__global__ void __launch_bounds__(THREADS) twp_kernel(
    const float4* __restrict__ x4,     // (B, T, 32) float4
    const float*  __restrict__ tw,
    const float*  __restrict__ mask,   // bool materialized as float32
    const float*  __restrict__ tw_uniq,
    float*        __restrict__ out)
{
    const int b    = blockIdx.y;
    const int t0   = blockIdx.x * TOK_PER_BLOCK;
    const int tid  = threadIdx.x;
    const int lane = tid & 31;
    const int row  = tid >> 5;

    __shared__ int seg_s[TOK_PER_BLOCK];

    const float twmin = tw_uniq[(size_t)b * TU_];

    if (tid < TOK_PER_BLOCK) {
        const int t = t0 + tid;
        int s = TU_;                                  // sentinel: never flushed
        if (mask[(size_t)b * T_ + t] != 0.0f) {
            s = (int)(tw[(size_t)b * T_ + t] - twmin);
            s = min(max(s, 0), TU_);
        }
        seg_s[tid] = s;
    }
    __syncthreads();

    // Branch-free load phase: all 4 token rows up front (MLP_p1 = 4).
    const float4* xp = x4 + ((size_t)b * T_ + t0 + row * TOK_PER_ROW) * LANES + lane;
    float4 v[TOK_PER_ROW];
    #pragma unroll
    for (int i = 0; i < TOK_PER_ROW; ++i)
        v[i] = xp[(size_t)i * LANES];

    unsigned int* outp = reinterpret_cast<unsigned int*>(out)
                         + (size_t)b * TU_ * DIM_ + lane * 4;

    const int sbase = row * TOK_PER_ROW;
    int cur = seg_s[sbase];
    float4 run = relu4(v[0]);

    #pragma unroll
    for (int i = 1; i < TOK_PER_ROW; ++i) {
        const int s = seg_s[sbase + i];
        if (s != cur) {
            if (cur < TU_)
                flush4(outp + (size_t)cur * DIM_, run);
            run = make_float4(0.0f, 0.0f, 0.0f, 0.0f);
            cur = s;
        }
        run = max4(run, relu4(v[i]));
    }
    if (cur < TU_)
        flush4(outp + (size_t)cur * DIM_, run);
}

extern "C" void kernel_launch(void* const* d_in, const int* in_sizes, int n_in,
                              void* d_out, int out_size)
{
    const float4* x4      = (const float4*)d_in[0];
    const float*  tw      = (const float*)d_in[1];
    const float*  mask    = (const float*)d_in[2];
    const float*  tw_uniq = (const float*)d_in[3];
    float*        out     = (float*)d_out;

    // Output poisoned to 0xAA (which compares HUGE as uint) — must zero first.
    cudaMemsetAsync(d_out, 0, (size_t)out_size * sizeof(float));

    dim3 grid(T_ / TOK_PER_BLOCK, B_);   // 64 x 8 = 512 blocks, 256 thr each
    twp_kernel<<<grid, THREADS>>>(x4, tw, mask, tw_uniq, out);
}